// round 3
// baseline (speedup 1.0000x reference)
#include <cuda_runtime.h>

// PCEN stack: per-row (B*P*F = 8192 rows, T = 2048) forward-backward EMA
// filtfilt for K=4 smoothing constants, softmax-weighted mix, PCEN epilogue.
//
// Parallel scan formulation: y[t] = s*x[t] + q*y[t-1] (q = 1-s) is a
// constant-coefficient linear recurrence. One block per row, 128 threads,
// each thread owns 16 contiguous elements. Local zero-init chain gives chunk
// end e_c; chunk carries satisfy G_c = e_c + Q*G_{c-1} with Q = q^16 -> warp
// Kogge-Stone scan (factor doubling) + tiny 4-warp fold (factor q^512).
// Then re-run the chain with the exact carry. Scaled-variable trick
// (y~ = y/s) makes each chain step a single FMA.
//
// Epilogue identities:
//   log(EPS) + log1p(M/EPS) = log(M + EPS)       -> M' = (M+EPS)^(-alpha)
//   (x*M'+d)^r - d^r = d^r * (exp(r*log1p(x*M'/d)) - 1)   (kills cancellation)

static __device__ __forceinline__ float sigmoidf_(float v) {
    return 1.0f / (1.0f + __expf(-v));
}

__global__ __launch_bounds__(128, 3)
void pcen_kernel(const float* __restrict__ x,
                 const float* __restrict__ i_sig_alpha,
                 const float* __restrict__ log_delta,
                 const float* __restrict__ i_sig_r,
                 const float* __restrict__ z_ks,
                 float* __restrict__ out,
                 int P, int F)
{
    constexpr int T  = 2048;
    constexpr int CH = 16;   // elements per thread
    constexpr int K  = 4;
    const float s_[K] = {0.015f, 0.04f, 0.1f, 0.25f};

    const int row  = blockIdx.x;            // ((b*P)+p)*F + f
    const int p    = (row / F) % P;
    const int f    = row % F;
    const int base = row * T;
    const int tid  = threadIdx.x;
    const int lane = tid & 31;
    const int w    = tid >> 5;

    // -------- per-k constants (computed in registers, all unrolled) --------
    float q_[K], is_[K], Q16[K], Q32[K], Qlf[K], Qlb[K];
#pragma unroll
    for (int k = 0; k < K; ++k) {
        q_[k]  = 1.0f - s_[k];
        is_[k] = 1.0f / s_[k];
        float Q = q_[k];
        Q *= Q; Q *= Q; Q *= Q; Q *= Q;            // q^16
        Q16[k] = Q;
        float R = Q; R *= R; R *= R; R *= R; R *= R; R *= R;   // q^512
        Q32[k] = R;
        // per-lane powers Q16^lane (fwd) and Q16^(31-lane) (bwd), binary pow
        float pf = 1.0f, pb = 1.0f, b = Q16[k];
        int ef = lane, eb = 31 - lane;
#pragma unroll
        for (int j = 0; j < 5; ++j) {
            if (ef & 1) pf *= b;
            if (eb & 1) pb *= b;
            ef >>= 1; eb >>= 1; b *= b;
        }
        Qlf[k] = pf; Qlb[k] = pb;
    }

    // -------- per-(p,f) scalars --------
    const float alpha     = sigmoidf_(i_sig_alpha[p]);
    const float rr        = sigmoidf_(i_sig_r[p]);
    const float ld        = log_delta[p];
    const float inv_delta = __expf(-ld);
    const float dr        = __expf(rr * ld);       // delta^r

    float zk[K];
#pragma unroll
    for (int k = 0; k < K; ++k) zk[k] = z_ks[(p * K + k) * F + f];
    float zm = fmaxf(fmaxf(zk[0], zk[1]), fmaxf(zk[2], zk[3]));
    float esum = 0.f, wk[K];
#pragma unroll
    for (int k = 0; k < K; ++k) { wk[k] = __expf(zk[k] - zm); esum += wk[k]; }
    const float inv_sum = 1.0f / esum;
    float ws2[K];                                  // w_k * s_k^2 (fold scaling)
#pragma unroll
    for (int k = 0; k < K; ++k) ws2[k] = wk[k] * inv_sum * s_[k] * s_[k];

    // -------- load x (16 contiguous floats per thread, 4x LDG.128) --------
    float xr[CH];
    const float4* xv = reinterpret_cast<const float4*>(x + base + tid * CH);
#pragma unroll
    for (int j = 0; j < CH / 4; ++j) {
        float4 v = xv[j];
        xr[4*j+0] = v.x; xr[4*j+1] = v.y; xr[4*j+2] = v.z; xr[4*j+3] = v.w;
    }

    __shared__ float smA[4][K];     // forward warp aggregates
    __shared__ float smB[4][K];     // backward warp aggregates
    __shared__ float smInit[K];     // backward init = y_fwd[T-1] per k
    __shared__ float smX0;          // forward init = x[0]

    // ==================== FORWARD filtfilt pass ====================
    // pass1: zero-init scaled chains (y~ = y/s): y~ = x + q*y~  (1 FMA/step)
    float S[K];
#pragma unroll
    for (int k = 0; k < K; ++k) S[k] = 0.f;
#pragma unroll
    for (int i = 0; i < CH; ++i)
#pragma unroll
        for (int k = 0; k < K; ++k) S[k] = fmaf(q_[k], S[k], xr[i]);
#pragma unroll
    for (int k = 0; k < K; ++k) S[k] *= s_[k];     // true-units chunk ends

    // warp inclusive scan: S_l = e_l + Q16 * S_{l-1}
    {
        float Qp[K];
#pragma unroll
        for (int k = 0; k < K; ++k) Qp[k] = Q16[k];
#pragma unroll
        for (int off = 1; off < 32; off <<= 1) {
#pragma unroll
            for (int k = 0; k < K; ++k) {
                float v = __shfl_up_sync(0xffffffffu, S[k], off);
                if (lane >= off) S[k] = fmaf(Qp[k], v, S[k]);
                Qp[k] *= Qp[k];
            }
        }
    }
    if (lane == 31) {
#pragma unroll
        for (int k = 0; k < K; ++k) smA[w][k] = S[k];
    }
    if (tid == 0) smX0 = xr[0];
    __syncthreads();

    // carry into this chunk: G_{c-1} = S_{lane-1} + Q16^lane * H_{w-1},
    // H_{w-1} folds warp aggregates with factor q^512, seeded by x[0].
    float carry[K];
#pragma unroll
    for (int k = 0; k < K; ++k) {
        float v  = __shfl_up_sync(0xffffffffu, S[k], 1);
        float sx = (lane > 0) ? v : 0.f;
        float H  = smX0;
#pragma unroll
        for (int j = 0; j < 3; ++j)
            if (j < w) H = fmaf(Q32[k], H, smA[j][k]);
        carry[k] = fmaf(Qlf[k], H, sx);
    }

    // pass2: chain with exact init, store y~ (scaled) as filtered signal
    float yf[K][CH];
    {
        float yt[K];
#pragma unroll
        for (int k = 0; k < K; ++k) yt[k] = carry[k] * is_[k];
#pragma unroll
        for (int i = 0; i < CH; ++i)
#pragma unroll
            for (int k = 0; k < K; ++k) {
                yt[k] = fmaf(q_[k], yt[k], xr[i]);
                yf[k][i] = yt[k];
            }
    }

    // ==================== BACKWARD filtfilt pass ====================
    // z# = z/s^2 satisfies z# = y~ + q*z#  (operates directly on stored y~)
    float Sb[K];
#pragma unroll
    for (int k = 0; k < K; ++k) Sb[k] = 0.f;
#pragma unroll
    for (int i = CH - 1; i >= 0; --i)
#pragma unroll
        for (int k = 0; k < K; ++k) Sb[k] = fmaf(q_[k], Sb[k], yf[k][i]);
#pragma unroll
    for (int k = 0; k < K; ++k) Sb[k] *= s_[k] * s_[k];   // true units

    // descending warp scan: S'_l = e'_l + Q16 * S'_{l+1}
    {
        float Qp[K];
#pragma unroll
        for (int k = 0; k < K; ++k) Qp[k] = Q16[k];
#pragma unroll
        for (int off = 1; off < 32; off <<= 1) {
#pragma unroll
            for (int k = 0; k < K; ++k) {
                float v = __shfl_down_sync(0xffffffffu, Sb[k], off);
                if (lane < 32 - off) Sb[k] = fmaf(Qp[k], v, Sb[k]);
                Qp[k] *= Qp[k];
            }
        }
    }
    if (lane == 0) {
#pragma unroll
        for (int k = 0; k < K; ++k) smB[w][k] = Sb[k];
    }
    if (tid == blockDim.x - 1) {
#pragma unroll
        for (int k = 0; k < K; ++k) smInit[k] = s_[k] * yf[k][CH - 1]; // y_fwd[T-1]
    }
    __syncthreads();

    float carryB[K];
#pragma unroll
    for (int k = 0; k < K; ++k) {
        float v  = __shfl_down_sync(0xffffffffu, Sb[k], 1);
        float sx = (lane < 31) ? v : 0.f;
        float H  = smInit[k];
#pragma unroll
        for (int j = 3; j >= 1; --j)
            if (j > w) H = fmaf(Q32[k], H, smB[j][k]);
        carryB[k] = fmaf(Qlb[k], H, sx);
    }

    // pass2 backward + fused mix + PCEN epilogue, write out
    float ob[CH];
    {
        float zt[K];
#pragma unroll
        for (int k = 0; k < K; ++k) zt[k] = carryB[k] * is_[k] * is_[k];
#pragma unroll
        for (int i = CH - 1; i >= 0; --i) {
            float M = 0.f;
#pragma unroll
            for (int k = 0; k < K; ++k) {
                zt[k] = fmaf(q_[k], zt[k], yf[k][i]);
                M = fmaf(ws2[k], zt[k], M);        // ws2 = w_k*s_k^2 -> true z
            }
            float Mp = __expf(-alpha * __logf(M + 1e-6f));   // (M+eps)^(-alpha)
            float t  = xr[i] * Mp * inv_delta;
            float o  = dr * (__expf(rr * __logf(1.0f + t)) - 1.0f);
            ob[i] = o;
        }
    }

    float4* ov = reinterpret_cast<float4*>(out + base + tid * CH);
#pragma unroll
    for (int j = 0; j < CH / 4; ++j)
        ov[j] = make_float4(ob[4*j+0], ob[4*j+1], ob[4*j+2], ob[4*j+3]);
}

extern "C" void kernel_launch(void* const* d_in, const int* in_sizes, int n_in,
                              void* d_out, int out_size)
{
    const float* x   = (const float*)d_in[0];
    const float* isa = (const float*)d_in[1];
    const float* ldl = (const float*)d_in[2];
    const float* isr = (const float*)d_in[3];
    const float* zks = (const float*)d_in[4];
    float* out = (float*)d_out;

    const int P    = in_sizes[1];                 // 4
    const int F    = in_sizes[4] / (P * 4);       // 128 (z_ks is [P,K,F], K=4)
    const int rows = in_sizes[0] / 2048;          // B*P*F = 8192

    pcen_kernel<<<rows, 128>>>(x, isa, ldl, isr, zks, out, P, F);
}